// round 1
// baseline (speedup 1.0000x reference)
#include <cuda_runtime.h>
#include <cstdint>

#define BB 8
#define DD 8
#define KK 5
#define PP (512*1024)

// ---- scratch (device globals: no allocation allowed) ----
__device__ float g_sums[BB][KK][DD];        // per-batch per-instance channel sums
__device__ int   g_cnt[BB][KK + 1];         // per-batch per-slot pixel counts (slot 0 = bg)
__device__ float g_var[BB][KK + 1];         // per-batch per-slot variance-term sums
__device__ float g_centers[BB][KK + 1][DD]; // slot 0 = zeros

// ---------------------------------------------------------------------------
__global__ void init_kernel() {
    int t = threadIdx.x;
    float* s = &g_sums[0][0][0];
    for (int i = t; i < BB * KK * DD; i += blockDim.x) s[i] = 0.f;
    int* c = &g_cnt[0][0];
    for (int i = t; i < BB * (KK + 1); i += blockDim.x) c[i] = 0;
    float* v = &g_var[0][0];
    for (int i = t; i < BB * (KK + 1); i += blockDim.x) v[i] = 0.f;
}

// ---------------------------------------------------------------------------
// Pass 1: per-instance channel sums + counts.
// Per-thread smem slots: 6 labels x 8 floats, stride 52 floats (208B, 16B-aligned,
// 13 (odd) 16B-groups -> decorrelated bank mapping for LDS.128).
#define T1 128
#define SLOT1 52
#define GX1 128

__global__ void __launch_bounds__(T1) pass1_kernel(const float* __restrict__ emb,
                                                   const int* __restrict__ mask) {
    __shared__ float acc[T1 * SLOT1];
    const int t = threadIdx.x;
    const int b = blockIdx.y;
    float* my = acc + t * SLOT1;
#pragma unroll
    for (int j = 0; j < SLOT1; j++) my[j] = 0.f;

    unsigned long long cnt64 = 0ull;
    const float* eb = emb + (size_t)b * DD * PP;
    const int*   mb = mask + (size_t)b * PP;
    const int stride = GX1 * T1 * 4;

    for (int p0 = (blockIdx.x * T1 + t) * 4; p0 < PP; p0 += stride) {
        const int4 lab4 = *reinterpret_cast<const int4*>(mb + p0);
        float ev[4][DD];
#pragma unroll
        for (int d = 0; d < DD; d++) {
            float4 v = *reinterpret_cast<const float4*>(eb + (size_t)d * PP + p0);
            ev[0][d] = v.x; ev[1][d] = v.y; ev[2][d] = v.z; ev[3][d] = v.w;
        }
        int labs[4] = {lab4.x, lab4.y, lab4.z, lab4.w};
#pragma unroll
        for (int i = 0; i < 4; i++) {
            const int lab = labs[i];
            cnt64 += 1ull << (lab * 8);
            float* slot = my + lab * 8;
            float4 lo = *reinterpret_cast<float4*>(slot);
            float4 hi = *reinterpret_cast<float4*>(slot + 4);
            lo.x += ev[i][0]; lo.y += ev[i][1]; lo.z += ev[i][2]; lo.w += ev[i][3];
            hi.x += ev[i][4]; hi.y += ev[i][5]; hi.z += ev[i][6]; hi.w += ev[i][7];
            *reinterpret_cast<float4*>(slot)     = lo;
            *reinterpret_cast<float4*>(slot + 4) = hi;
        }
    }

    __syncthreads();
    // tree-reduce the 40 useful floats (labels 1..5) across threads
    for (int off = T1 / 2; off > 0; off >>= 1) {
        if (t < off) {
            float* a = acc + t * SLOT1;
            float* c = acc + (t + off) * SLOT1;
#pragma unroll
            for (int j = 8; j < 48; j++) a[j] += c[j];
        }
        __syncthreads();
    }
    if (t < KK * DD) atomicAdd(&g_sums[b][0][0] + t, acc[8 + t]);

    // counts: warp REDUX then per-warp atomic
#pragma unroll
    for (int k = 1; k <= KK; k++) {
        unsigned c = (unsigned)((cnt64 >> (8 * k)) & 0xffull);
        c = __reduce_add_sync(0xffffffffu, c);
        if ((t & 31) == 0) atomicAdd(&g_cnt[b][k], (int)c);
    }
}

// ---------------------------------------------------------------------------
__global__ void centers_kernel() {
    int t = threadIdx.x;
    if (t < BB * (KK + 1) * DD) {
        int b = t / ((KK + 1) * DD);
        int r = t % ((KK + 1) * DD);
        int slot = r / DD, d = r % DD;
        float v = 0.f;
        if (slot >= 1) {
            float cnt = (float)g_cnt[b][slot];
            v = g_sums[b][slot - 1][d] / fmaxf(cnt, 1.f);
        }
        g_centers[b][slot][d] = v;
    }
}

// ---------------------------------------------------------------------------
// Pass 2: per-pixel hinge-variance term accumulated per instance.
#define T2 256
#define VSLOT 9
#define GX2 128

__device__ __forceinline__ float fsqrt_approx(float x) {
    float r;
    asm("sqrt.approx.f32 %0, %1;" : "=f"(r) : "f"(x));
    return r;
}

__global__ void __launch_bounds__(T2) pass2_kernel(const float* __restrict__ emb,
                                                   const int* __restrict__ mask) {
    __shared__ float4 cs4[(KK + 1) * 2];   // centers table, float4-aligned
    __shared__ float vacc[T2 * VSLOT];
    const int t = threadIdx.x;
    const int b = blockIdx.y;
    if (t < (KK + 1) * DD) {
        reinterpret_cast<float*>(cs4)[t] = (&g_centers[b][0][0])[t];
    }
#pragma unroll
    for (int j = 0; j < VSLOT; j++) vacc[t * VSLOT + j] = 0.f;
    __syncthreads();

    const float* eb = emb + (size_t)b * DD * PP;
    const int*   mb = mask + (size_t)b * PP;
    const int stride = GX2 * T2 * 4;

    for (int p0 = (blockIdx.x * T2 + t) * 4; p0 < PP; p0 += stride) {
        const int4 lab4 = *reinterpret_cast<const int4*>(mb + p0);
        float ev[4][DD];
#pragma unroll
        for (int d = 0; d < DD; d++) {
            float4 v = *reinterpret_cast<const float4*>(eb + (size_t)d * PP + p0);
            ev[0][d] = v.x; ev[1][d] = v.y; ev[2][d] = v.z; ev[3][d] = v.w;
        }
        int labs[4] = {lab4.x, lab4.y, lab4.z, lab4.w};
#pragma unroll
        for (int i = 0; i < 4; i++) {
            const int lab = labs[i];
            const float4 clo = cs4[lab * 2];
            const float4 chi = cs4[lab * 2 + 1];
            float d0 = ev[i][0] - clo.x;
            float s  = d0 * d0;
            float d1 = ev[i][1] - clo.y; s = fmaf(d1, d1, s);
            float d2 = ev[i][2] - clo.z; s = fmaf(d2, d2, s);
            float d3 = ev[i][3] - clo.w; s = fmaf(d3, d3, s);
            float d4 = ev[i][4] - chi.x; s = fmaf(d4, d4, s);
            float d5 = ev[i][5] - chi.y; s = fmaf(d5, d5, s);
            float d6 = ev[i][6] - chi.z; s = fmaf(d6, d6, s);
            float d7 = ev[i][7] - chi.w; s = fmaf(d7, d7, s);
            // max(sqrt(s)-0.5,0)^2 == s - sqrt(s) + 0.25 when s > 0.25 else 0
            float val = (s - fsqrt_approx(s)) + 0.25f;
            val = (s > 0.25f) ? val : 0.f;
            vacc[t * VSLOT + lab] += val;
        }
    }

    __syncthreads();
    for (int off = T2 / 2; off > 0; off >>= 1) {
        if (t < off) {
            float* a = vacc + t * VSLOT;
            float* c = vacc + (t + off) * VSLOT;
#pragma unroll
            for (int j = 0; j < 6; j++) a[j] += c[j];
        }
        __syncthreads();
    }
    if (t >= 1 && t <= KK) atomicAdd(&g_var[b][t], vacc[t]);
}

// ---------------------------------------------------------------------------
__global__ void finalize_kernel(float* __restrict__ out) {
    __shared__ float s_var[BB], s_dist[BB], s_reg[BB], s_has[BB];
    const int t = threadIdx.x;
    if (t < BB) {
        const int b = t;
        float cnt[KK], present[KK], N = 0.f;
#pragma unroll
        for (int k = 0; k < KK; k++) {
            cnt[k] = (float)g_cnt[b][k + 1];
            present[k] = cnt[k] > 0.f ? 1.f : 0.f;
            N += present[k];
        }
        // variance loss
        float lv = 0.f;
#pragma unroll
        for (int k = 0; k < KK; k++)
            lv += present[k] * (g_var[b][k + 1] / fmaxf(cnt[k], 1.f));
        lv /= fmaxf(N, 1.f);
        // distance loss
        float ld = 0.f;
        for (int i = 0; i < KK; i++) {
            for (int j = i + 1; j < KK; j++) {
                if (present[i] > 0.f && present[j] > 0.f) {
                    float dsq = 0.f;
#pragma unroll
                    for (int d = 0; d < DD; d++) {
                        float df = g_centers[b][i + 1][d] - g_centers[b][j + 1][d];
                        dsq = fmaf(df, df, dsq);
                    }
                    float dist = sqrtf(dsq);
                    float term = fmaxf(6.0f - dist, 0.f);  // 2*DELTA_D = 6
                    ld += term * term;
                }
            }
        }
        float npairs = N * (N - 1.f) * 0.5f;
        ld /= (N > 1.f) ? npairs : 1.f;
        // regularization
        float lr = 0.f;
#pragma unroll
        for (int k = 0; k < KK; k++) {
            if (present[k] > 0.f) {
                float nsq = 0.f;
#pragma unroll
                for (int d = 0; d < DD; d++) {
                    float c = g_centers[b][k + 1][d];
                    nsq = fmaf(c, c, nsq);
                }
                lr += sqrtf(nsq);
            }
        }
        lr /= fmaxf(N, 1.f);
        s_var[b] = lv; s_dist[b] = ld; s_reg[b] = lr;
        s_has[b] = (N > 0.f) ? 1.f : 0.f;
    }
    __syncthreads();
    if (t == 0) {
        float hv = 0.f, hd = 0.f, hr = 0.f, hh = 0.f;
#pragma unroll
        for (int b = 0; b < BB; b++) {
            hh += s_has[b];
            hv += s_var[b] * s_has[b];
            hd += s_dist[b] * s_has[b];
            hr += s_reg[b] * s_has[b];
        }
        const float den = fmaxf(hh, 1.f);
        const float var = hv / den, dist = hd / den, reg = hr / den;
        out[0] = var + dist + 0.001f * reg;  // ALPHA=BETA=1, GAMMA=0.001
        out[1] = var;
        out[2] = dist;
        out[3] = reg;
    }
}

// ---------------------------------------------------------------------------
extern "C" void kernel_launch(void* const* d_in, const int* in_sizes, int n_in,
                              void* d_out, int out_size) {
    const float* emb  = (const float*)d_in[0];
    const int*   mask = (const int*)d_in[1];
    float*       out  = (float*)d_out;

    init_kernel<<<1, 256>>>();
    dim3 g1(GX1, BB);
    pass1_kernel<<<g1, T1>>>(emb, mask);
    centers_kernel<<<1, 384>>>();
    dim3 g2(GX2, BB);
    pass2_kernel<<<g2, T2>>>(emb, mask);
    finalize_kernel<<<1, 32>>>(out);
}